// round 13
// baseline (speedup 1.0000x reference)
#include <cuda_runtime.h>
#include <cuda_fp16.h>
#include <cstdint>

#define EMB  1024
#define NH   16
#define HD   64
#define BSZ  4
#define SEQ  2048
#define BH   (BSZ*NH)

// fp16 scratch
__device__ __half g_qh[BH*SEQ*HD];
__device__ __half g_kh[BH*SEQ*HD];
__device__ __half g_vh[BH*SEQ*HD];
__device__ __half g_xh[BSZ*SEQ*EMB];
__device__ __half g_wqkvh[3*EMB*EMB];
__device__ __half g_woh[EMB*EMB];
__device__ __half g_mh[BSZ*SEQ*EMB];

__device__ __forceinline__ uint32_t h2u(__half2 h) {
    union { __half2 h; uint32_t u; } c; c.h = h; return c.u;
}
__device__ __forceinline__ uint32_t smem_u32(const void* p) {
    uint32_t a;
    asm("{ .reg .u64 t; cvta.to.shared.u64 t, %1; cvt.u32.u64 %0, t; }" : "=r"(a) : "l"(p));
    return a;
}
__device__ __forceinline__ uint64_t gptr(const void* p) {
    uint64_t r; asm("cvta.to.global.u64 %0, %1;" : "=l"(r) : "l"(p)); return r;
}
__device__ __forceinline__ void mma_f16(float* c, const uint32_t* a, uint32_t b0, uint32_t b1) {
    asm volatile(
        "mma.sync.aligned.m16n8k16.row.col.f32.f16.f16.f32 "
        "{%0,%1,%2,%3}, {%4,%5,%6,%7}, {%8,%9}, {%0,%1,%2,%3};"
        : "+f"(c[0]), "+f"(c[1]), "+f"(c[2]), "+f"(c[3])
        : "r"(a[0]), "r"(a[1]), "r"(a[2]), "r"(a[3]), "r"(b0), "r"(b1));
}
__device__ __forceinline__ void ldsm4(uint32_t* r, uint32_t addr) {
    asm volatile("ldmatrix.sync.aligned.m8n8.x4.shared.b16 {%0,%1,%2,%3}, [%4];"
                 : "=r"(r[0]), "=r"(r[1]), "=r"(r[2]), "=r"(r[3]) : "r"(addr));
}
__device__ __forceinline__ void ldsm4t(uint32_t* r, uint32_t addr) {
    asm volatile("ldmatrix.sync.aligned.m8n8.x4.trans.shared.b16 {%0,%1,%2,%3}, [%4];"
                 : "=r"(r[0]), "=r"(r[1]), "=r"(r[2]), "=r"(r[3]) : "r"(addr));
}
__device__ __forceinline__ void cpasync16(uint32_t dst, uint64_t src) {
    asm volatile("cp.async.cg.shared.global [%0], [%1], 16;" :: "r"(dst), "l"(src));
}
__device__ __forceinline__ float ex2f(float x) {
    float y; asm("ex2.approx.ftz.f32 %0, %1;" : "=f"(y) : "f"(x)); return y;
}

// ---------------------------------------------------------------------------
// Fused fp32->fp16 convert: x + Wq + Wk + Wv + Wo in one launch.
// ---------------------------------------------------------------------------
__global__ void f2h_all(const float4* __restrict__ x,
                        const float4* __restrict__ wq, const float4* __restrict__ wk,
                        const float4* __restrict__ wv, const float4* __restrict__ wo,
                        __half2* __restrict__ xh, __half2* __restrict__ wqkvh,
                        __half2* __restrict__ woh)
{
    const int NX4 = (BSZ*SEQ*EMB)/4;    // 2097152
    const int NW4 = (EMB*EMB)/4;        // 262144 = 2^18
    int i = blockIdx.x * blockDim.x + threadIdx.x;
    const float4* src; __half2* dst; int off;
    if (i < NX4) { src = x; dst = xh; off = i; }
    else {
        int j = i - NX4;
        int w = j >> 18; off = j & (NW4 - 1);
        src = (w == 0) ? wq : (w == 1) ? wk : (w == 2) ? wv : wo;
        dst = (w == 3) ? woh : wqkvh + (size_t)w * 2 * NW4;
    }
    float4 v = src[off];
    dst[2*off]   = __floats2half2_rn(v.x, v.y);
    dst[2*off+1] = __floats2half2_rn(v.z, v.w);
}

// ---------------------------------------------------------------------------
// QKV GEMM: 256x128 CTA tile, 3-stage cp.async, warp tile 64x64.
// C written fp16 head-split into Qh/Kh/Vh (selected by n>>10).
// ---------------------------------------------------------------------------
#define TGB_NST   3
#define TGB_ASZ   (256*128)
#define TGB_BSZ   (128*128)
#define TGB_STAGE (TGB_ASZ + TGB_BSZ)
#define TGB_SMEM  (TGB_NST * TGB_STAGE)   // 147456

__global__ void __launch_bounds__(256) tgemm_qkv(const __half* __restrict__ A,
                                                 const __half* __restrict__ W,
                                                 __half* __restrict__ Qh,
                                                 __half* __restrict__ Kh,
                                                 __half* __restrict__ Vh,
                                                 int M, int N, int K)
{
    extern __shared__ __align__(16) char smc[];
    const int tid = threadIdx.x, lane = tid & 31, wid = tid >> 5;
    const int wm = wid & 3, wn = wid >> 2;
    const int bm = blockIdx.y * 256, bn = blockIdx.x * 128;
    const uint32_t sbase = smem_u32(smc);

    const uint64_t gA = gptr(A) + (size_t)bm * K * 2;
    const uint64_t gB = gptr(W) + (size_t)bn * K * 2;

    const int cr = tid >> 3, cc8 = tid & 7;
    const uint32_t csw = ((uint32_t)(cc8 * 16)) ^ (((uint32_t)cr & 7) << 4);

    float acc[4][8][4];
#pragma unroll
    for (int i = 0; i < 4; i++)
#pragma unroll
        for (int j = 0; j < 8; j++)
#pragma unroll
            for (int r = 0; r < 4; r++) acc[i][j][r] = 0.f;

    const int KIT = K / 64;   // 16

#define TGB_ISSUE(kt, s)                                                          \
    do {                                                                          \
        uint32_t sA = sbase + (s) * TGB_STAGE;                                    \
        uint32_t sB = sA + TGB_ASZ;                                               \
        uint64_t goff = ((size_t)(kt) * 64 + cc8 * 8) * 2;                        \
        _Pragma("unroll")                                                         \
        for (int i = 0; i < 8; i++) {                                             \
            int r = cr + i * 32;                                                  \
            cpasync16(sA + r * 128 + csw, gA + (size_t)r * K * 2 + goff);         \
        }                                                                         \
        _Pragma("unroll")                                                         \
        for (int i = 0; i < 4; i++) {                                             \
            int r = cr + i * 32;                                                  \
            cpasync16(sB + r * 128 + csw, gB + (size_t)r * K * 2 + goff);         \
        }                                                                         \
        asm volatile("cp.async.commit_group;");                                   \
    } while (0)

    TGB_ISSUE(0, 0);
    TGB_ISSUE(1, 1);

    const int l8 = lane & 7;
    const int rowA0 = wm * 64 + l8 + 8 * ((lane >> 3) & 1);
    const int colA0 = 16 * (lane >> 4);
    const uint32_t xorA = ((uint32_t)rowA0 & 7) << 4;
    const int rowB0 = wn * 64 + l8 + 8 * (lane >> 4);
    const int colB0 = 16 * ((lane >> 3) & 1);
    const uint32_t xorB = ((uint32_t)rowB0 & 7) << 4;

    for (int it = 0; it < KIT; it++) {
        asm volatile("cp.async.wait_group 1;");
        __syncthreads();

        if (it + 2 < KIT) { TGB_ISSUE(it + 2, (it + 2) % TGB_NST); }
        else { asm volatile("cp.async.commit_group;"); }

        const uint32_t aT = sbase + (it % TGB_NST) * TGB_STAGE;
        const uint32_t bT = aT + TGB_ASZ;

#pragma unroll
        for (int ks = 0; ks < 4; ks++) {
            uint32_t af[4][4], bf[8][2];
#pragma unroll
            for (int mt = 0; mt < 4; mt++)
                ldsm4(af[mt], aT + (rowA0 + mt * 16) * 128 + ((ks * 32 + colA0) ^ xorA));
#pragma unroll
            for (int j2 = 0; j2 < 4; j2++) {
                uint32_t r[4];
                ldsm4(r, bT + (rowB0 + j2 * 16) * 128 + ((ks * 32 + colB0) ^ xorB));
                bf[j2*2][0] = r[0]; bf[j2*2][1] = r[1];
                bf[j2*2+1][0] = r[2]; bf[j2*2+1][1] = r[3];
            }
#pragma unroll
            for (int mt = 0; mt < 4; mt++)
#pragma unroll
                for (int nt = 0; nt < 8; nt++)
                    mma_f16(acc[mt][nt], af[mt], bf[nt][0], bf[nt][1]);
        }
    }
#undef TGB_ISSUE

#pragma unroll
    for (int mt = 0; mt < 4; mt++) {
#pragma unroll
        for (int nt = 0; nt < 8; nt++) {
            const int m0 = bm + wm * 64 + mt * 16 + (lane >> 2);
            const int n0 = bn + wn * 64 + nt * 8 + (lane & 3) * 2;
            const int which = n0 >> 10;
            __half* base = (which == 0) ? Qh : (which == 1) ? Kh : Vh;
            const int nl = n0 & 1023;
            const int h = nl >> 6, d = nl & 63;
            const int b0 = m0 >> 11, s0 = m0 & (SEQ - 1);
            *(__half2*)(base + ((size_t)((b0*NH + h)*SEQ + s0) << 6) + d) =
                __floats2half2_rn(acc[mt][nt][0], acc[mt][nt][1]);
            const int m1 = m0 + 8;
            const int b1 = m1 >> 11, s1 = m1 & (SEQ - 1);
            *(__half2*)(base + ((size_t)((b1*NH + h)*SEQ + s1) << 6) + d) =
                __floats2half2_rn(acc[mt][nt][2], acc[mt][nt][3]);
        }
    }
}

// ---------------------------------------------------------------------------
// Wo GEMM: 128x128 tile, 4-stage cp.async (round-11 kernel, MODE0 only).
// ---------------------------------------------------------------------------
#define TGH_SMEM (4 * 32768)

__global__ void __launch_bounds__(256) tgemm_wo(const __half* __restrict__ A,
                                                const __half* __restrict__ W,
                                                float* __restrict__ Cf,
                                                int M, int N, int K)
{
    extern __shared__ __align__(16) char smc[];
    const int tid = threadIdx.x, lane = tid & 31, wid = tid >> 5;
    const int wm = wid & 1, wn = wid >> 1;
    const int bm = blockIdx.y * 128, bn = blockIdx.x * 128;
    const uint32_t sbase = smem_u32(smc);

    const uint64_t gA = gptr(A) + (size_t)bm * K * 2;
    const uint64_t gB = gptr(W) + (size_t)bn * K * 2;

    const int cr = tid >> 3, cc8 = tid & 7;
    const uint32_t csw = ((uint32_t)(cc8 * 16)) ^ (((uint32_t)cr & 7) << 4);

    float acc[4][4][4];
#pragma unroll
    for (int i = 0; i < 4; i++)
#pragma unroll
        for (int j = 0; j < 4; j++)
#pragma unroll
            for (int r = 0; r < 4; r++) acc[i][j][r] = 0.f;

    const int KIT = K / 64;

#define TGH_ISSUE(kt, s)                                                          \
    do {                                                                          \
        uint32_t sA = sbase + (s) * 32768;                                        \
        uint64_t goff = ((size_t)(kt) * 64 + cc8 * 8) * 2;                        \
        _Pragma("unroll")                                                         \
        for (int i = 0; i < 4; i++) {                                             \
            int r = cr + i * 32;                                                  \
            uint32_t so = sA + r * 128 + csw;                                     \
            cpasync16(so,         gA + (size_t)r * K * 2 + goff);                 \
            cpasync16(so + 16384, gB + (size_t)r * K * 2 + goff);                 \
        }                                                                         \
        asm volatile("cp.async.commit_group;");                                   \
    } while (0)

    TGH_ISSUE(0, 0);
    TGH_ISSUE(1, 1);
    TGH_ISSUE(2, 2);

    const int l8 = lane & 7;
    const int rowA0 = wm * 64 + l8 + 8 * ((lane >> 3) & 1);
    const int colA0 = 16 * (lane >> 4);
    const uint32_t xorA = ((uint32_t)rowA0 & 7) << 4;
    const int rowB0 = wn * 32 + l8 + 8 * (lane >> 4);
    const int colB0 = 16 * ((lane >> 3) & 1);
    const uint32_t xorB = ((uint32_t)rowB0 & 7) << 4;

    for (int it = 0; it < KIT; it++) {
        asm volatile("cp.async.wait_group 2;");
        __syncthreads();

        const uint32_t aT = sbase + (it & 3) * 32768;
        const uint32_t bT = aT + 16384;

#pragma unroll
        for (int ks = 0; ks < 4; ks++) {
            uint32_t af[4][4], bf[4][2];
#pragma unroll
            for (int mt = 0; mt < 4; mt++)
                ldsm4(af[mt], aT + (rowA0 + mt * 16) * 128 + ((ks * 32 + colA0) ^ xorA));
#pragma unroll
            for (int j2 = 0; j2 < 2; j2++) {
                uint32_t r[4];
                ldsm4(r, bT + (rowB0 + j2 * 16) * 128 + ((ks * 32 + colB0) ^ xorB));
                bf[j2*2][0] = r[0]; bf[j2*2][1] = r[1];
                bf[j2*2+1][0] = r[2]; bf[j2*2+1][1] = r[3];
            }
#pragma unroll
            for (int mt = 0; mt < 4; mt++)
#pragma unroll
                for (int nt = 0; nt < 4; nt++)
                    mma_f16(acc[mt][nt], af[mt], bf[nt][0], bf[nt][1]);
        }

        if (it + 3 < KIT) { TGH_ISSUE(it + 3, (it + 3) & 3); }
        else { asm volatile("cp.async.commit_group;"); }
    }
#undef TGH_ISSUE

#pragma unroll
    for (int i = 0; i < 4; i++) {
#pragma unroll
        for (int j = 0; j < 4; j++) {
            const int m0 = bm + wm * 64 + i * 16 + (lane >> 2);
            const int n0 = bn + wn * 32 + j * 8 + (lane & 3) * 2;
            float2 lo = { acc[i][j][0], acc[i][j][1] };
            float2 hi = { acc[i][j][2], acc[i][j][3] };
            *(float2*)(Cf + (size_t)m0 * N + n0) = lo;
            *(float2*)(Cf + (size_t)(m0 + 8) * N + n0) = hi;
        }
    }
}

// ---------------------------------------------------------------------------
// fp16 flash attention: cp.async 3-stage K/V + ldmatrix(.trans) + m16n8k16.
// ---------------------------------------------------------------------------
#define NST   3
#define KVST  (64*128)
#define ATT_SMEM (NST*2*KVST + 128*128)

__global__ void __launch_bounds__(256) attn_tc(const __half* __restrict__ Qg,
                                               const __half* __restrict__ Kg,
                                               const __half* __restrict__ Vg,
                                               __half* __restrict__ Out)
{
    extern __shared__ __align__(16) char smc[];
    const uint32_t sbase = smem_u32(smc);
    const uint32_t qsm   = sbase + NST*2*KVST;

    const int qt = (SEQ/128 - 1) - blockIdx.x;
    const int bh = blockIdx.y;
    const int b = bh >> 4, h = bh & 15;
    const int tid = threadIdx.x, w = tid >> 5, lane = tid & 31;
    const int g = lane >> 2, t = lane & 3;
    const int l8 = lane & 7;

    const uint64_t gQ = gptr(Qg) + (size_t)(bh*SEQ + qt*128)*HD*2;
    const uint64_t gK = gptr(Kg) + (size_t)bh*SEQ*HD*2;
    const uint64_t gV = gptr(Vg) + (size_t)bh*SEQ*HD*2;

    const int cr = tid >> 3, cc = tid & 7;
    const int nkt = 2*qt + 2;

#pragma unroll
    for (int i = 0; i < 4; i++) {
        int r = cr + i*32;
        cpasync16(qsm + r*128 + ((cc ^ (r & 7)) << 4), gQ + (size_t)r*128 + cc*16);
    }
    asm volatile("cp.async.commit_group;");

#define KV_ISSUE(kt_)                                                             \
    do {                                                                          \
        if ((kt_) < nkt) {                                                        \
            uint32_t ks_ = sbase + ((kt_) % NST) * 2 * KVST;                      \
            size_t go = (size_t)(kt_) * 64;                                       \
            _Pragma("unroll")                                                     \
            for (int i = 0; i < 2; i++) {                                         \
                int r = cr + i*32;                                                \
                uint32_t sw = ((cc ^ (r & 7)) << 4);                              \
                cpasync16(ks_ + r*128 + sw,        gK + (go + r)*128 + cc*16);    \
                cpasync16(ks_ + KVST + r*128 + sw, gV + (go + r)*128 + cc*16);    \
            }                                                                     \
        }                                                                         \
        asm volatile("cp.async.commit_group;");                                   \
    } while (0)

    KV_ISSUE(0);
    KV_ISSUE(1);

    asm volatile("cp.async.wait_group 2;");
    __syncthreads();

    uint32_t qf[4][4];
    {
        const int r = w*16 + l8 + 8*((lane >> 3) & 1);
        const uint32_t rb = qsm + r*128;
        const uint32_t xr = ((uint32_t)r & 7);
#pragma unroll
        for (int ks = 0; ks < 4; ks++)
            ldsm4(qf[ks], rb + (((uint32_t)(2*ks + (lane >> 4)) ^ xr) << 4));
    }

    float mrow[2] = { -1e30f, -1e30f };
    float lrow[2] = { 0.f, 0.f };
    float oacc[8][4];
#pragma unroll
    for (int i = 0; i < 8; i++)
#pragma unroll
        for (int r = 0; r < 4; r++) oacc[i][r] = 0.f;

    const int rK = l8 + ((lane >> 4) << 3);
    const int rV = l8 + (((lane >> 3) & 1) << 3);

    for (int kt = 0; kt < nkt; kt++) {
        asm volatile("cp.async.wait_group 1;");
        __syncthreads();
        KV_ISSUE(kt + 2);

        const uint32_t Kst = sbase + (kt % NST) * 2 * KVST;
        const uint32_t Vst = Kst + KVST;

        float sacc[8][4];
#pragma unroll
        for (int nt = 0; nt < 8; nt++)
#pragma unroll
            for (int r = 0; r < 4; r++) sacc[nt][r] = 0.f;

#pragma unroll
        for (int ks = 0; ks < 4; ks++) {
            const uint32_t ch = 2*ks + ((lane >> 3) & 1);
#pragma unroll
            for (int ntp = 0; ntp < 4; ntp++) {
                const int key = ntp*16 + rK;
                uint32_t r4[4];
                ldsm4(r4, Kst + key*128 + ((ch ^ ((uint32_t)key & 7)) << 4));
                mma_f16(sacc[2*ntp],   qf[ks], r4[0], r4[1]);
                mma_f16(sacc[2*ntp+1], qf[ks], r4[2], r4[3]);
            }
        }

        const float SC = 0.125f * 1.44269504088896340736f;
#pragma unroll
        for (int nt = 0; nt < 8; nt++)
#pragma unroll
            for (int r = 0; r < 4; r++) sacc[nt][r] *= SC;

        if (kt >= 2*qt) {
            const int row0 = qt*128 + w*16 + g;
            const int colb = kt*64 + 2*t;
#pragma unroll
            for (int nt = 0; nt < 8; nt++) {
                int c = colb + nt*8;
                if (c     > row0)     sacc[nt][0] = -1e30f;
                if (c + 1 > row0)     sacc[nt][1] = -1e30f;
                if (c     > row0 + 8) sacc[nt][2] = -1e30f;
                if (c + 1 > row0 + 8) sacc[nt][3] = -1e30f;
            }
        }

#pragma unroll
        for (int hh = 0; hh < 2; hh++) {
            const int i0 = hh*2;
            float mx = -1e30f;
#pragma unroll
            for (int nt = 0; nt < 8; nt++)
                mx = fmaxf(mx, fmaxf(sacc[nt][i0], sacc[nt][i0+1]));
            mx = fmaxf(mx, __shfl_xor_sync(0xffffffffu, mx, 1));
            mx = fmaxf(mx, __shfl_xor_sync(0xffffffffu, mx, 2));
            float mnew = fmaxf(mrow[hh], mx);
            float corr = ex2f(mrow[hh] - mnew);
            mrow[hh] = mnew;
            float sum = 0.f;
#pragma unroll
            for (int nt = 0; nt < 8; nt++) {
                sacc[nt][i0]   = ex2f(sacc[nt][i0]   - mnew);
                sacc[nt][i0+1] = ex2f(sacc[nt][i0+1] - mnew);
                sum += sacc[nt][i0] + sacc[nt][i0+1];
            }
            sum += __shfl_xor_sync(0xffffffffu, sum, 1);
            sum += __shfl_xor_sync(0xffffffffu, sum, 2);
            lrow[hh] = lrow[hh]*corr + sum;
#pragma unroll
            for (int dt = 0; dt < 8; dt++) {
                oacc[dt][i0]   *= corr;
                oacc[dt][i0+1] *= corr;
            }
        }

#pragma unroll
        for (int ksV = 0; ksV < 4; ksV++) {
            uint32_t pf[4];
            pf[0] = h2u(__floats2half2_rn(sacc[2*ksV][0],   sacc[2*ksV][1]));
            pf[1] = h2u(__floats2half2_rn(sacc[2*ksV][2],   sacc[2*ksV][3]));
            pf[2] = h2u(__floats2half2_rn(sacc[2*ksV+1][0], sacc[2*ksV+1][1]));
            pf[3] = h2u(__floats2half2_rn(sacc[2*ksV+1][2], sacc[2*ksV+1][3]));
            const int row = ksV*16 + rV;
            const uint32_t rb = Vst + row*128;
            const uint32_t xr = (uint32_t)row & 7;
#pragma unroll
            for (int dtp = 0; dtp < 4; dtp++) {
                uint32_t r4[4];
                ldsm4t(r4, rb + (((uint32_t)(2*dtp + (lane >> 4)) ^ xr) << 4));
                mma_f16(oacc[2*dtp],   pf, r4[0], r4[1]);
                mma_f16(oacc[2*dtp+1], pf, r4[2], r4[3]);
            }
        }
    }
#undef KV_ISSUE

    const float inv0 = 1.0f / lrow[0];
    const float inv1 = 1.0f / lrow[1];
    const int row0 = qt*128 + w*16 + g;
#pragma unroll
    for (int dt = 0; dt < 8; dt++) {
        const int col = h*64 + dt*8 + 2*t;
        *(__half2*)(Out + (size_t)(b*SEQ + row0)*EMB + col) =
            __floats2half2_rn(oacc[dt][0]*inv0, oacc[dt][1]*inv0);
        *(__half2*)(Out + (size_t)(b*SEQ + row0 + 8)*EMB + col) =
            __floats2half2_rn(oacc[dt][2]*inv1, oacc[dt][3]*inv1);
    }
}

extern "C" void kernel_launch(void* const* d_in, const int* in_sizes, int n_in,
                              void* d_out, int out_size)
{
    const float* x  = (const float*)d_in[0];
    const float* Wq = (const float*)d_in[1];
    const float* Wk = (const float*)d_in[2];
    const float* Wv = (const float*)d_in[3];
    const float* Wo = (const float*)d_in[4];
    float* out = (float*)d_out;

    __half *qh, *kh, *vh, *xh, *wqkvh, *woh, *mh;
    cudaGetSymbolAddress((void**)&qh, g_qh);
    cudaGetSymbolAddress((void**)&kh, g_kh);
    cudaGetSymbolAddress((void**)&vh, g_vh);
    cudaGetSymbolAddress((void**)&xh, g_xh);
    cudaGetSymbolAddress((void**)&wqkvh, g_wqkvh);
    cudaGetSymbolAddress((void**)&woh, g_woh);
    cudaGetSymbolAddress((void**)&mh, g_mh);

    const int M = BSZ*SEQ, K = EMB;
    const int TOT4 = (M*K)/4 + 4*(EMB*EMB)/4;

    f2h_all<<<(TOT4+255)/256, 256>>>((const float4*)x, (const float4*)Wq,
                                     (const float4*)Wk, (const float4*)Wv,
                                     (const float4*)Wo,
                                     (__half2*)xh, (__half2*)wqkvh, (__half2*)woh);

    cudaFuncSetAttribute(tgemm_qkv, cudaFuncAttributeMaxDynamicSharedMemorySize, TGB_SMEM);
    cudaFuncSetAttribute(tgemm_wo,  cudaFuncAttributeMaxDynamicSharedMemorySize, TGH_SMEM);
    cudaFuncSetAttribute(attn_tc,   cudaFuncAttributeMaxDynamicSharedMemorySize, ATT_SMEM);

    tgemm_qkv<<<dim3(3*EMB/128, M/256), 256, TGB_SMEM>>>(xh, wqkvh, qh, kh, vh, M, 3*EMB, K);

    attn_tc<<<dim3(SEQ/128, BH), 256, ATT_SMEM>>>(qh, kh, vh, mh);

    tgemm_wo<<<dim3(EMB/128, M/128), 256, TGH_SMEM>>>(mh, woh, out, M, EMB, K);
}

// round 14
// speedup vs baseline: 1.1139x; 1.1139x over previous
#include <cuda_runtime.h>
#include <cuda_fp16.h>
#include <cstdint>

#define EMB  1024
#define NH   16
#define HD   64
#define BSZ  4
#define SEQ  2048
#define BH   (BSZ*NH)

// fp16 scratch
__device__ __half g_qh[BH*SEQ*HD];
__device__ __half g_kh[BH*SEQ*HD];
__device__ __half g_vh[BH*SEQ*HD];
__device__ __half g_xh[BSZ*SEQ*EMB];
__device__ __half g_wqkvh[3*EMB*EMB];
__device__ __half g_woh[EMB*EMB];
__device__ __half g_mh[BSZ*SEQ*EMB];

__device__ __forceinline__ uint32_t h2u(__half2 h) {
    union { __half2 h; uint32_t u; } c; c.h = h; return c.u;
}
__device__ __forceinline__ uint32_t smem_u32(const void* p) {
    uint32_t a;
    asm("{ .reg .u64 t; cvta.to.shared.u64 t, %1; cvt.u32.u64 %0, t; }" : "=r"(a) : "l"(p));
    return a;
}
__device__ __forceinline__ uint64_t gptr(const void* p) {
    uint64_t r; asm("cvta.to.global.u64 %0, %1;" : "=l"(r) : "l"(p)); return r;
}
__device__ __forceinline__ void mma_f16(float* c, const uint32_t* a, uint32_t b0, uint32_t b1) {
    asm volatile(
        "mma.sync.aligned.m16n8k16.row.col.f32.f16.f16.f32 "
        "{%0,%1,%2,%3}, {%4,%5,%6,%7}, {%8,%9}, {%0,%1,%2,%3};"
        : "+f"(c[0]), "+f"(c[1]), "+f"(c[2]), "+f"(c[3])
        : "r"(a[0]), "r"(a[1]), "r"(a[2]), "r"(a[3]), "r"(b0), "r"(b1));
}
__device__ __forceinline__ void ldsm4(uint32_t* r, uint32_t addr) {
    asm volatile("ldmatrix.sync.aligned.m8n8.x4.shared.b16 {%0,%1,%2,%3}, [%4];"
                 : "=r"(r[0]), "=r"(r[1]), "=r"(r[2]), "=r"(r[3]) : "r"(addr));
}
__device__ __forceinline__ void ldsm4t(uint32_t* r, uint32_t addr) {
    asm volatile("ldmatrix.sync.aligned.m8n8.x4.trans.shared.b16 {%0,%1,%2,%3}, [%4];"
                 : "=r"(r[0]), "=r"(r[1]), "=r"(r[2]), "=r"(r[3]) : "r"(addr));
}
__device__ __forceinline__ void cpasync16(uint32_t dst, uint64_t src) {
    asm volatile("cp.async.cg.shared.global [%0], [%1], 16;" :: "r"(dst), "l"(src));
}
__device__ __forceinline__ float ex2f(float x) {
    float y; asm("ex2.approx.ftz.f32 %0, %1;" : "=f"(y) : "f"(x)); return y;
}

// ---------------------------------------------------------------------------
// Fused fp32->fp16 convert
// ---------------------------------------------------------------------------
__global__ void f2h_all(const float4* __restrict__ x,
                        const float4* __restrict__ wq, const float4* __restrict__ wk,
                        const float4* __restrict__ wv, const float4* __restrict__ wo,
                        __half2* __restrict__ xh, __half2* __restrict__ wqkvh,
                        __half2* __restrict__ woh)
{
    const int NX4 = (BSZ*SEQ*EMB)/4;
    const int NW4 = (EMB*EMB)/4;
    int i = blockIdx.x * blockDim.x + threadIdx.x;
    const float4* src; __half2* dst; int off;
    if (i < NX4) { src = x; dst = xh; off = i; }
    else {
        int j = i - NX4;
        int w = j >> 18; off = j & (NW4 - 1);
        src = (w == 0) ? wq : (w == 1) ? wk : (w == 2) ? wv : wo;
        dst = (w == 3) ? woh : wqkvh + (size_t)w * 2 * NW4;
    }
    float4 v = src[off];
    dst[2*off]   = __floats2half2_rn(v.x, v.y);
    dst[2*off+1] = __floats2half2_rn(v.z, v.w);
}

// ---------------------------------------------------------------------------
// fp16 GEMM, 128x128 tile, 3-stage cp.async (96KB smem) => 2 CTAs/SM.
// MODE 0: fp32 out row-major.  MODE 1: fp16 out head-split into Qh/Kh/Vh.
// ---------------------------------------------------------------------------
#define TGH_NST   3
#define TGH_STAGE 32768
#define TGH_SMEM  (TGH_NST * TGH_STAGE)   // 98304

template<int MODE>
__global__ void __launch_bounds__(256, 2) tgemm_h(const __half* __restrict__ A,
                                                  const __half* __restrict__ W,
                                                  float* __restrict__ Cf,
                                                  __half* __restrict__ Qh,
                                                  __half* __restrict__ Kh,
                                                  __half* __restrict__ Vh,
                                                  int M, int N, int K)
{
    extern __shared__ __align__(16) char smc[];
    const int tid = threadIdx.x, lane = tid & 31, wid = tid >> 5;
    const int wm = wid & 1, wn = wid >> 1;
    const int bm = blockIdx.y * 128, bn = blockIdx.x * 128;
    const uint32_t sbase = smem_u32(smc);

    const uint64_t gA = gptr(A) + (size_t)bm * K * 2;
    const uint64_t gB = gptr(W) + (size_t)bn * K * 2;

    const int cr = tid >> 3, cc8 = tid & 7;
    const uint32_t csw = ((uint32_t)(cc8 * 16)) ^ (((uint32_t)cr & 7) << 4);

    float acc[4][4][4];
#pragma unroll
    for (int i = 0; i < 4; i++)
#pragma unroll
        for (int j = 0; j < 4; j++)
#pragma unroll
            for (int r = 0; r < 4; r++) acc[i][j][r] = 0.f;

    const int KIT = K / 64;

#define TGH_ISSUE(kt, s)                                                          \
    do {                                                                          \
        uint32_t sA = sbase + (s) * TGH_STAGE;                                    \
        uint64_t goff = ((size_t)(kt) * 64 + cc8 * 8) * 2;                        \
        _Pragma("unroll")                                                         \
        for (int i = 0; i < 4; i++) {                                             \
            int r = cr + i * 32;                                                  \
            uint32_t so = sA + r * 128 + csw;                                     \
            cpasync16(so,         gA + (size_t)r * K * 2 + goff);                 \
            cpasync16(so + 16384, gB + (size_t)r * K * 2 + goff);                 \
        }                                                                         \
        asm volatile("cp.async.commit_group;");                                   \
    } while (0)

    TGH_ISSUE(0, 0);
    TGH_ISSUE(1, 1);

    const int l8 = lane & 7;
    const int rowA0 = wm * 64 + l8 + 8 * ((lane >> 3) & 1);
    const int colA0 = 16 * (lane >> 4);
    const uint32_t xorA = ((uint32_t)rowA0 & 7) << 4;
    const int rowB0 = wn * 32 + l8 + 8 * (lane >> 4);
    const int colB0 = 16 * ((lane >> 3) & 1);
    const uint32_t xorB = ((uint32_t)rowB0 & 7) << 4;

    for (int it = 0; it < KIT; it++) {
        asm volatile("cp.async.wait_group 1;");
        __syncthreads();

        if (it + 2 < KIT) { TGH_ISSUE(it + 2, (it + 2) % TGH_NST); }
        else { asm volatile("cp.async.commit_group;"); }

        const uint32_t aT = sbase + (it % TGH_NST) * TGH_STAGE;
        const uint32_t bT = aT + 16384;

#pragma unroll
        for (int ks = 0; ks < 4; ks++) {
            uint32_t af[4][4], bf[4][2];
#pragma unroll
            for (int mt = 0; mt < 4; mt++)
                ldsm4(af[mt], aT + (rowA0 + mt * 16) * 128 + ((ks * 32 + colA0) ^ xorA));
#pragma unroll
            for (int j2 = 0; j2 < 2; j2++) {
                uint32_t r[4];
                ldsm4(r, bT + (rowB0 + j2 * 16) * 128 + ((ks * 32 + colB0) ^ xorB));
                bf[j2*2][0] = r[0]; bf[j2*2][1] = r[1];
                bf[j2*2+1][0] = r[2]; bf[j2*2+1][1] = r[3];
            }
#pragma unroll
            for (int mt = 0; mt < 4; mt++)
#pragma unroll
                for (int nt = 0; nt < 4; nt++)
                    mma_f16(acc[mt][nt], af[mt], bf[nt][0], bf[nt][1]);
        }
    }
#undef TGH_ISSUE

#pragma unroll
    for (int i = 0; i < 4; i++) {
#pragma unroll
        for (int j = 0; j < 4; j++) {
            const int m0 = bm + wm * 64 + i * 16 + (lane >> 2);
            const int n0 = bn + wn * 32 + j * 8 + (lane & 3) * 2;
            if (MODE == 0) {
                float2 lo = { acc[i][j][0], acc[i][j][1] };
                float2 hi = { acc[i][j][2], acc[i][j][3] };
                *(float2*)(Cf + (size_t)m0 * N + n0) = lo;
                *(float2*)(Cf + (size_t)(m0 + 8) * N + n0) = hi;
            } else {
                const int which = n0 >> 10;
                __half* base = (which == 0) ? Qh : (which == 1) ? Kh : Vh;
                const int nl = n0 & 1023;
                const int h = nl >> 6, d = nl & 63;
                const int b0 = m0 >> 11, s0 = m0 & (SEQ - 1);
                *(__half2*)(base + ((size_t)((b0*NH + h)*SEQ + s0) << 6) + d) =
                    __floats2half2_rn(acc[i][j][0], acc[i][j][1]);
                const int m1 = m0 + 8;
                const int b1 = m1 >> 11, s1 = m1 & (SEQ - 1);
                *(__half2*)(base + ((size_t)((b1*NH + h)*SEQ + s1) << 6) + d) =
                    __floats2half2_rn(acc[i][j][2], acc[i][j][3]);
            }
        }
    }
}

// ---------------------------------------------------------------------------
// fp16 flash attention: cp.async 3-stage K/V + ldmatrix(.trans) + m16n8k16.
// ---------------------------------------------------------------------------
#define NST   3
#define KVST  (64*128)
#define ATT_SMEM (NST*2*KVST + 128*128)

__global__ void __launch_bounds__(256) attn_tc(const __half* __restrict__ Qg,
                                               const __half* __restrict__ Kg,
                                               const __half* __restrict__ Vg,
                                               __half* __restrict__ Out)
{
    extern __shared__ __align__(16) char smc[];
    const uint32_t sbase = smem_u32(smc);
    const uint32_t qsm   = sbase + NST*2*KVST;

    const int qt = (SEQ/128 - 1) - blockIdx.x;
    const int bh = blockIdx.y;
    const int b = bh >> 4, h = bh & 15;
    const int tid = threadIdx.x, w = tid >> 5, lane = tid & 31;
    const int g = lane >> 2, t = lane & 3;
    const int l8 = lane & 7;

    const uint64_t gQ = gptr(Qg) + (size_t)(bh*SEQ + qt*128)*HD*2;
    const uint64_t gK = gptr(Kg) + (size_t)bh*SEQ*HD*2;
    const uint64_t gV = gptr(Vg) + (size_t)bh*SEQ*HD*2;

    const int cr = tid >> 3, cc = tid & 7;
    const int nkt = 2*qt + 2;

#pragma unroll
    for (int i = 0; i < 4; i++) {
        int r = cr + i*32;
        cpasync16(qsm + r*128 + ((cc ^ (r & 7)) << 4), gQ + (size_t)r*128 + cc*16);
    }
    asm volatile("cp.async.commit_group;");

#define KV_ISSUE(kt_)                                                             \
    do {                                                                          \
        if ((kt_) < nkt) {                                                        \
            uint32_t ks_ = sbase + ((kt_) % NST) * 2 * KVST;                      \
            size_t go = (size_t)(kt_) * 64;                                       \
            _Pragma("unroll")                                                     \
            for (int i = 0; i < 2; i++) {                                         \
                int r = cr + i*32;                                                \
                uint32_t sw = ((cc ^ (r & 7)) << 4);                              \
                cpasync16(ks_ + r*128 + sw,        gK + (go + r)*128 + cc*16);    \
                cpasync16(ks_ + KVST + r*128 + sw, gV + (go + r)*128 + cc*16);    \
            }                                                                     \
        }                                                                         \
        asm volatile("cp.async.commit_group;");                                   \
    } while (0)

    KV_ISSUE(0);
    KV_ISSUE(1);

    asm volatile("cp.async.wait_group 2;");
    __syncthreads();

    uint32_t qf[4][4];
    {
        const int r = w*16 + l8 + 8*((lane >> 3) & 1);
        const uint32_t rb = qsm + r*128;
        const uint32_t xr = ((uint32_t)r & 7);
#pragma unroll
        for (int ks = 0; ks < 4; ks++)
            ldsm4(qf[ks], rb + (((uint32_t)(2*ks + (lane >> 4)) ^ xr) << 4));
    }

    float mrow[2] = { -1e30f, -1e30f };
    float lrow[2] = { 0.f, 0.f };
    float oacc[8][4];
#pragma unroll
    for (int i = 0; i < 8; i++)
#pragma unroll
        for (int r = 0; r < 4; r++) oacc[i][r] = 0.f;

    const int rK = l8 + ((lane >> 4) << 3);
    const int rV = l8 + (((lane >> 3) & 1) << 3);

    for (int kt = 0; kt < nkt; kt++) {
        asm volatile("cp.async.wait_group 1;");
        __syncthreads();
        KV_ISSUE(kt + 2);

        const uint32_t Kst = sbase + (kt % NST) * 2 * KVST;
        const uint32_t Vst = Kst + KVST;

        float sacc[8][4];
#pragma unroll
        for (int nt = 0; nt < 8; nt++)
#pragma unroll
            for (int r = 0; r < 4; r++) sacc[nt][r] = 0.f;

#pragma unroll
        for (int ks = 0; ks < 4; ks++) {
            const uint32_t ch = 2*ks + ((lane >> 3) & 1);
#pragma unroll
            for (int ntp = 0; ntp < 4; ntp++) {
                const int key = ntp*16 + rK;
                uint32_t r4[4];
                ldsm4(r4, Kst + key*128 + ((ch ^ ((uint32_t)key & 7)) << 4));
                mma_f16(sacc[2*ntp],   qf[ks], r4[0], r4[1]);
                mma_f16(sacc[2*ntp+1], qf[ks], r4[2], r4[3]);
            }
        }

        const float SC = 0.125f * 1.44269504088896340736f;
#pragma unroll
        for (int nt = 0; nt < 8; nt++)
#pragma unroll
            for (int r = 0; r < 4; r++) sacc[nt][r] *= SC;

        if (kt >= 2*qt) {
            const int row0 = qt*128 + w*16 + g;
            const int colb = kt*64 + 2*t;
#pragma unroll
            for (int nt = 0; nt < 8; nt++) {
                int c = colb + nt*8;
                if (c     > row0)     sacc[nt][0] = -1e30f;
                if (c + 1 > row0)     sacc[nt][1] = -1e30f;
                if (c     > row0 + 8) sacc[nt][2] = -1e30f;
                if (c + 1 > row0 + 8) sacc[nt][3] = -1e30f;
            }
        }

#pragma unroll
        for (int hh = 0; hh < 2; hh++) {
            const int i0 = hh*2;
            float mx = -1e30f;
#pragma unroll
            for (int nt = 0; nt < 8; nt++)
                mx = fmaxf(mx, fmaxf(sacc[nt][i0], sacc[nt][i0+1]));
            mx = fmaxf(mx, __shfl_xor_sync(0xffffffffu, mx, 1));
            mx = fmaxf(mx, __shfl_xor_sync(0xffffffffu, mx, 2));
            float mnew = fmaxf(mrow[hh], mx);
            float corr = ex2f(mrow[hh] - mnew);
            mrow[hh] = mnew;
            float sum = 0.f;
#pragma unroll
            for (int nt = 0; nt < 8; nt++) {
                sacc[nt][i0]   = ex2f(sacc[nt][i0]   - mnew);
                sacc[nt][i0+1] = ex2f(sacc[nt][i0+1] - mnew);
                sum += sacc[nt][i0] + sacc[nt][i0+1];
            }
            sum += __shfl_xor_sync(0xffffffffu, sum, 1);
            sum += __shfl_xor_sync(0xffffffffu, sum, 2);
            lrow[hh] = lrow[hh]*corr + sum;
#pragma unroll
            for (int dt = 0; dt < 8; dt++) {
                oacc[dt][i0]   *= corr;
                oacc[dt][i0+1] *= corr;
            }
        }

#pragma unroll
        for (int ksV = 0; ksV < 4; ksV++) {
            uint32_t pf[4];
            pf[0] = h2u(__floats2half2_rn(sacc[2*ksV][0],   sacc[2*ksV][1]));
            pf[1] = h2u(__floats2half2_rn(sacc[2*ksV][2],   sacc[2*ksV][3]));
            pf[2] = h2u(__floats2half2_rn(sacc[2*ksV+1][0], sacc[2*ksV+1][1]));
            pf[3] = h2u(__floats2half2_rn(sacc[2*ksV+1][2], sacc[2*ksV+1][3]));
            const int row = ksV*16 + rV;
            const uint32_t rb = Vst + row*128;
            const uint32_t xr = (uint32_t)row & 7;
#pragma unroll
            for (int dtp = 0; dtp < 4; dtp++) {
                uint32_t r4[4];
                ldsm4t(r4, rb + (((uint32_t)(2*dtp + (lane >> 4)) ^ xr) << 4));
                mma_f16(oacc[2*dtp],   pf, r4[0], r4[1]);
                mma_f16(oacc[2*dtp+1], pf, r4[2], r4[3]);
            }
        }
    }
#undef KV_ISSUE

    const float inv0 = 1.0f / lrow[0];
    const float inv1 = 1.0f / lrow[1];
    const int row0 = qt*128 + w*16 + g;
#pragma unroll
    for (int dt = 0; dt < 8; dt++) {
        const int col = h*64 + dt*8 + 2*t;
        *(__half2*)(Out + (size_t)(b*SEQ + row0)*EMB + col) =
            __floats2half2_rn(oacc[dt][0]*inv0, oacc[dt][1]*inv0);
        *(__half2*)(Out + (size_t)(b*SEQ + row0 + 8)*EMB + col) =
            __floats2half2_rn(oacc[dt][2]*inv1, oacc[dt][3]*inv1);
    }
}

extern "C" void kernel_launch(void* const* d_in, const int* in_sizes, int n_in,
                              void* d_out, int out_size)
{
    const float* x  = (const float*)d_in[0];
    const float* Wq = (const float*)d_in[1];
    const float* Wk = (const float*)d_in[2];
    const float* Wv = (const float*)d_in[3];
    const float* Wo = (const float*)d_in[4];
    float* out = (float*)d_out;

    __half *qh, *kh, *vh, *xh, *wqkvh, *woh, *mh;
    cudaGetSymbolAddress((void**)&qh, g_qh);
    cudaGetSymbolAddress((void**)&kh, g_kh);
    cudaGetSymbolAddress((void**)&vh, g_vh);
    cudaGetSymbolAddress((void**)&xh, g_xh);
    cudaGetSymbolAddress((void**)&wqkvh, g_wqkvh);
    cudaGetSymbolAddress((void**)&woh, g_woh);
    cudaGetSymbolAddress((void**)&mh, g_mh);

    const int M = BSZ*SEQ, K = EMB;
    const int TOT4 = (M*K)/4 + 4*(EMB*EMB)/4;

    f2h_all<<<(TOT4+255)/256, 256>>>((const float4*)x, (const float4*)Wq,
                                     (const float4*)Wk, (const float4*)Wv,
                                     (const float4*)Wo,
                                     (__half2*)xh, (__half2*)wqkvh, (__half2*)woh);

    cudaFuncSetAttribute(tgemm_h<0>, cudaFuncAttributeMaxDynamicSharedMemorySize, TGH_SMEM);
    cudaFuncSetAttribute(tgemm_h<1>, cudaFuncAttributeMaxDynamicSharedMemorySize, TGH_SMEM);
    cudaFuncSetAttribute(attn_tc,    cudaFuncAttributeMaxDynamicSharedMemorySize, ATT_SMEM);

    tgemm_h<1><<<dim3(3*EMB/128, M/128), 256, TGH_SMEM>>>(xh, wqkvh, nullptr, qh, kh, vh, M, 3*EMB, K);

    attn_tc<<<dim3(SEQ/128, BH), 256, ATT_SMEM>>>(qh, kh, vh, mh);

    tgemm_h<0><<<dim3(EMB/128, M/128), 256, TGH_SMEM>>>(mh, woh, out, nullptr, nullptr, nullptr, M, EMB, K);
}